// round 16
// baseline (speedup 1.0000x reference)
#include <cuda_runtime.h>
#include <cstdint>

#define NCTA     125
#define ROWS     16
#define NTHREADS 288         // 8 matvec warps + 1 poller warp
#define RDIM     2000
#define XDIM     28
#define TSTEPS   28
#define BATCH    512
#define NSTEP    (BATCH*TSTEPS)
#define ODIM     10
#define NGRP     8           // 8 column groups of 256 cols = 16 producer CTAs

// Static device scratch (zero-initialized; reset_kernel restores for next replay)
__device__ __align__(16) float g_h[2][2048];   // double-buffered hidden state
__device__ float    g_hlast[BATCH*RDIM];       // h at t = T-1 per batch element
__device__ unsigned g_ctr[NGRP * 32];          // per-group counters, 128B apart

// ---- packed f32x2 helpers ----
__device__ __forceinline__ unsigned long long fma2(unsigned long long a,
                                                   unsigned long long b,
                                                   unsigned long long c) {
    unsigned long long d;
    asm("fma.rn.f32x2 %0, %1, %2, %3;" : "=l"(d) : "l"(a), "l"(b), "l"(c));
    return d;
}
__device__ __forceinline__ unsigned long long mul2(unsigned long long a,
                                                   unsigned long long b) {
    unsigned long long d;
    asm("mul.rn.f32x2 %0, %1, %2;" : "=l"(d) : "l"(a), "l"(b));
    return d;
}
__device__ __forceinline__ unsigned long long pk2(float lo, float hi) {
    unsigned long long u;
    asm("mov.b64 %0, {%1, %2};" : "=l"(u)
        : "r"(__float_as_uint(lo)), "r"(__float_as_uint(hi)));
    return u;
}
__device__ __forceinline__ float lo32(unsigned long long v) { return __uint_as_float((unsigned)v); }
__device__ __forceinline__ float hi32(unsigned long long v) { return __uint_as_float((unsigned)(v >> 32)); }

// Single acquire poll load on global counter (R5/R11-proven; FROZEN)
__device__ __forceinline__ unsigned ld_acq(const unsigned* p) {
    unsigned v;
    asm volatile("ld.acquire.gpu.u32 %0, [%1];" : "=r"(v) : "l"(p) : "memory");
    return v;
}
// SMEM flag ops (cta-scope release/acquire pair, poller -> consumers)
__device__ __forceinline__ void st_rel_sh(unsigned saddr, unsigned v) {
    asm volatile("st.release.cta.shared.u32 [%0], %1;"
                 :: "r"(saddr), "r"(v) : "memory");
}
__device__ __forceinline__ unsigned ld_acq_sh(unsigned saddr) {
    unsigned v;
    asm volatile("ld.acquire.cta.shared.u32 %0, [%1];"
                 : "=r"(v) : "r"(saddr) : "memory");
    return v;
}

// Fast tanh: (e^{2x}-1)/(e^{2x}+1) via MUFU.EX2 + MUFU.RCP (R14-validated).
__device__ __forceinline__ float ftanh(float s) {
    s = fminf(fmaxf(s, -20.0f), 20.0f);
    float e;
    asm("ex2.approx.f32 %0, %1;" : "=f"(e) : "f"(s * 2.885390082f)); // 2*log2(e)*x
    float r;
    asm("rcp.approx.f32 %0, %1;" : "=f"(r) : "f"(e + 1.0f));
    return (e - 1.0f) * r;
}

// W_ext element: [W_res | W_in | 0-pad], row r, extended column c
__device__ __forceinline__ float wext(const float* __restrict__ Wres,
                                      const float* __restrict__ Win,
                                      int r, int c) {
    if (c < RDIM)        return Wres[r * RDIM + c];
    if (c < RDIM + XDIM) return Win[r * XDIM + (c - RDIM)];
    return 0.0f;
}

// R1-validated register reduce-scatter stage
template <int M, int HALF>
__device__ __forceinline__ void rs_stage(float* a, int l) {
    const bool up = (l & M) != 0;
#pragma unroll
    for (int i = 0; i < HALF; ++i) {
        float send = up ? a[i] : a[i + HALF];
        float recv = __shfl_xor_sync(0xffffffffu, send, M);
        a[i] = (up ? a[i + HALF] : a[i]) + recv;
    }
}

__global__ void __launch_bounds__(NTHREADS, 1)
rnn_kernel(const float* __restrict__ x,
           const float* __restrict__ W_in,
           const float* __restrict__ W_res) {
    // Transposed partials (R14): spart[parity][row][warp], padded to 12 so the
    // publisher reads each row as two conflict-free LDS.128.
    __shared__ __align__(16) float spart[2][ROWS][12];
    __shared__ unsigned sflag[NGRP];    // monotonic per-group step flags

    const int tid   = threadIdx.x;
    const int w     = tid >> 5;
    const int l     = tid & 31;
    const int rbase = blockIdx.x * ROWS;

    if (tid < NGRP) sflag[tid] = 0u;
    __syncthreads();                    // one-time: sflag init visible to all

    // ================= poller warp (warp 8) =================
    if (w == 8) {
        if (l < NGRP) {
            const unsigned png = (l < 7) ? 16u : 13u;
            const unsigned* pcp = &g_ctr[l * 32];
            const unsigned fs = (unsigned)__cvta_generic_to_shared(&sflag[l]);
            unsigned ptgt = png;                    // target for step 1
            for (int s = 1; s < NSTEP; ++s) {
                while (ld_acq(pcp) < ptgt) { }
                st_rel_sh(fs, (unsigned)s);         // announce h_{s-1} ready
                ptgt += png;
            }
        }
        return;
    }

    // ================= matvec warps (w < 8) =================
    const int c0 = w * 256 + l * 4;             // lane's column base (R1 layout)
    const bool xlane = (w == 7) && (l >= 20) && (l < 27);  // cols 2000..2027 <- x
    const bool zlane = (w == 7) && (l >= 27);              // cols 2028..2047 <- 0

    // ---- W_ext slice in registers (R1 gather, 128 regs) ----
    unsigned long long W2[ROWS][4];
#pragma unroll
    for (int r = 0; r < ROWS; ++r) {
        const int gr = rbase + r;
#pragma unroll
        for (int q = 0; q < 4; ++q) {
            const int c = c0 + (q >> 1) * 128 + (q & 1) * 2;
            W2[r][q] = pk2(wext(W_res, W_in, gr, c),
                           wext(W_res, W_in, gr, c + 1));
        }
    }

    unsigned* __restrict__ ap = &g_ctr[(blockIdx.x >> 4) * 32];
    const unsigned fs = (unsigned)__cvta_generic_to_shared(&sflag[w]);

    // prefetch x_0 for x-duty lanes
    ulonglong2 xr = make_ulonglong2(0ull, 0ull);
    if (xlane) {
        const float4 xv = __ldg((const float4*)(x) + (l - 20));
        xr.x = pk2(xv.x, xv.y);
        xr.y = pk2(xv.z, xv.w);
    }

    for (int s = 0; s < NSTEP; ++s) {
        // ---- gate: fast SMEM flag wait (poller tracks the global counter) ----
        unsigned tok;
        while ((tok = ld_acq_sh(fs)) < (unsigned)s) { }

        // ---- load h: address opaquely depends on the flag token ----
        const float* buf = g_h[(s + 1) & 1];
        asm volatile("" : "+l"(buf) : "r"(tok));
        const ulonglong2 ha = __ldcg((const ulonglong2*)(buf + c0));
        ulonglong2 hb;
        if (xlane) {
            hb = xr;                        // x_s prefetched last iteration
        } else if (zlane) {
            hb.x = 0ull;  hb.y = 0ull;      // zero pad cols 2028..2047
        } else {
            hb = __ldcg((const ulonglong2*)(buf + c0 + 128));
        }
        if (xlane && s + 1 < NSTEP) {       // prefetch x_{s+1} off critical path
            const float4 xv = __ldg((const float4*)(x + (size_t)(s + 1) * XDIM) + (l - 20));
            xr.x = pk2(xv.x, xv.y);
            xr.y = pk2(xv.z, xv.w);
        }

        // ---- matvec: 16 rows x 8 cols per lane, packed f32x2 (R1 order) ----
        unsigned long long acc[ROWS];
#pragma unroll
        for (int r = 0; r < ROWS; ++r) acc[r] = mul2(W2[r][0], ha.x);
#pragma unroll
        for (int r = 0; r < ROWS; ++r) acc[r] = fma2(W2[r][1], ha.y, acc[r]);
#pragma unroll
        for (int r = 0; r < ROWS; ++r) acc[r] = fma2(W2[r][2], hb.x, acc[r]);
#pragma unroll
        for (int r = 0; r < ROWS; ++r) acc[r] = fma2(W2[r][3], hb.y, acc[r]);

        float a[ROWS];
#pragma unroll
        for (int r = 0; r < ROWS; ++r) a[r] = lo32(acc[r]) + hi32(acc[r]);

        // ---- R1-validated warp reduce-scatter (16 rows over 32 lanes) ----
        rs_stage<16, 8>(a, l);
        rs_stage<8, 4>(a, l);
        rs_stage<4, 2>(a, l);
        rs_stage<2, 1>(a, l);
        const float pv = a[0] + __shfl_xor_sync(0xffffffffu, a[0], 1);

        // parity double-buffer write (no front barrier; R11-proven)
        if ((l & 1) == 0) spart[s & 1][l >> 1][w] = pv;

        // ---- split barrier (R14): non-publishers arrive and run ahead ----
        const int bid = 1 + (s & 1);
        if (w != 0) {
            asm volatile("bar.arrive %0, %1;" :: "r"(bid), "r"(256) : "memory");
            continue;   // straight to next-step flag wait
        }
        asm volatile("bar.sync %0, %1;" :: "r"(bid), "r"(256) : "memory");

        // ---- warp 0: combine (LDS.128 x2) + tanh + publish + release ----
        {
            float hv = 0.0f;
            if (l < ROWS) {
                const float4 p0 = *(const float4*)&spart[s & 1][l][0];
                const float4 p1 = *(const float4*)&spart[s & 1][l][4];
                const float sum = ((p0.x + p0.y) + (p0.z + p0.w))
                                + ((p1.x + p1.y) + (p1.z + p1.w));
                hv = ftanh(sum);
                __stcg(&g_h[s & 1][rbase + l], hv);
            }
            __syncwarp();
            if (l == 0)
                asm volatile("red.release.gpu.global.add.u32 [%0], %1;"
                             :: "l"(ap), "r"(1u) : "memory");
            // hlast after release: only out_kernel (next launch) reads it
            if (l < ROWS && (s % TSTEPS) == TSTEPS - 1)
                g_hlast[(s / TSTEPS) * RDIM + rbase + l] = hv;
        }
    }
}

__global__ void out_kernel(const float* __restrict__ W_out,
                           float* __restrict__ out) {
    const int b   = blockIdx.x;
    const int tid = threadIdx.x;
    const float* __restrict__ h = g_hlast + b * RDIM;

    float acc[ODIM];
#pragma unroll
    for (int o = 0; o < ODIM; ++o) acc[o] = 0.f;

    for (int k = tid; k < RDIM; k += 256) {
        const float hv = h[k];
#pragma unroll
        for (int o = 0; o < ODIM; ++o)
            acc[o] = fmaf(W_out[o * RDIM + k], hv, acc[o]);
    }
#pragma unroll
    for (int o = 0; o < ODIM; ++o) {
#pragma unroll
        for (int m = 16; m >= 1; m >>= 1)
            acc[o] += __shfl_xor_sync(0xffffffffu, acc[o], m);
    }
    __shared__ float sp[8][ODIM];
    if ((tid & 31) == 0) {
#pragma unroll
        for (int o = 0; o < ODIM; ++o) sp[tid >> 5][o] = acc[o];
    }
    __syncthreads();
    if (tid < ODIM) {
        float s2 = 0.f;
#pragma unroll
        for (int ww = 0; ww < 8; ++ww) s2 += sp[ww][tid];
        out[b * ODIM + tid] = s2;
    }
}

__global__ void reset_kernel() {   // restores state for the NEXT replay
    const int t = blockIdx.x * blockDim.x + threadIdx.x;
    if (t < NGRP * 32) g_ctr[t] = 0u;
    if (t < RDIM)      g_h[1][t] = 0.0f;   // h0 = 0 (buffer read by step 0)
}

extern "C" void kernel_launch(void* const* d_in, const int* in_sizes, int n_in,
                              void* d_out, int out_size) {
    (void)in_sizes; (void)n_in; (void)out_size;
    const float* x     = (const float*)d_in[0];
    const float* W_in  = (const float*)d_in[1];
    const float* W_res = (const float*)d_in[2];
    const float* W_out = (const float*)d_in[3];
    float* out = (float*)d_out;

    // Order (rnn, out, reset): profiler lands on rnn; reset prepares the next
    // replay; first launch relies on zero-initialized device globals.
    rnn_kernel<<<NCTA, NTHREADS>>>(x, W_in, W_res);  // 125 CTAs, 1/SM
    out_kernel<<<BATCH, 256>>>(W_out, out);
    reset_kernel<<<8, 256>>>();
}

// round 17
// speedup vs baseline: 1.0485x; 1.0485x over previous
#include <cuda_runtime.h>
#include <cstdint>

#define NCTA     125
#define ROWS     16
#define NTHREADS 256         // 8 warps; warp w reads h cols [256w, 256w+256)
#define RDIM     2000
#define XDIM     28
#define TSTEPS   28
#define BATCH    512
#define NSTEP    (BATCH*TSTEPS)
#define ODIM     10
#define NGRP     8           // 8 column groups of 256 cols = 16 producer CTAs

// Static device scratch (zero-initialized; reset_kernel restores for next replay)
__device__ __align__(16) float g_h[2][2048];   // cols 2000..2047 stay 0 forever
__device__ float    g_hlast[BATCH*RDIM];       // h at t = T-1 per batch element
__device__ unsigned g_ctr[NGRP * 32];          // per-group counters, 128B apart
__device__ __align__(16) float g_u[(size_t)NCTA * NSTEP * ROWS];  // u = W_in x

// ---- packed f32x2 helpers ----
__device__ __forceinline__ unsigned long long fma2(unsigned long long a,
                                                   unsigned long long b,
                                                   unsigned long long c) {
    unsigned long long d;
    asm("fma.rn.f32x2 %0, %1, %2, %3;" : "=l"(d) : "l"(a), "l"(b), "l"(c));
    return d;
}
__device__ __forceinline__ unsigned long long mul2(unsigned long long a,
                                                   unsigned long long b) {
    unsigned long long d;
    asm("mul.rn.f32x2 %0, %1, %2;" : "=l"(d) : "l"(a), "l"(b));
    return d;
}
__device__ __forceinline__ unsigned long long pk2(float lo, float hi) {
    unsigned long long u;
    asm("mov.b64 %0, {%1, %2};" : "=l"(u)
        : "r"(__float_as_uint(lo)), "r"(__float_as_uint(hi)));
    return u;
}
__device__ __forceinline__ float lo32(unsigned long long v) { return __uint_as_float((unsigned)v); }
__device__ __forceinline__ float hi32(unsigned long long v) { return __uint_as_float((unsigned)(v >> 32)); }

// Single acquire poll load (R5/R11/R14-proven gate; FROZEN)
__device__ __forceinline__ unsigned ld_acq(const unsigned* p) {
    unsigned v;
    asm volatile("ld.acquire.gpu.u32 %0, [%1];" : "=r"(v) : "l"(p) : "memory");
    return v;
}

// Fast tanh: (e^{2x}-1)/(e^{2x}+1) via MUFU.EX2 + MUFU.RCP (R14-validated).
__device__ __forceinline__ float ftanh(float s) {
    s = fminf(fmaxf(s, -20.0f), 20.0f);
    float e;
    asm("ex2.approx.f32 %0, %1;" : "=f"(e) : "f"(s * 2.885390082f)); // 2*log2(e)*x
    float r;
    asm("rcp.approx.f32 %0, %1;" : "=f"(r) : "f"(e + 1.0f));
    return (e - 1.0f) * r;
}

// R1-validated register reduce-scatter stage
template <int M, int HALF>
__device__ __forceinline__ void rs_stage(float* a, int l) {
    const bool up = (l & M) != 0;
#pragma unroll
    for (int i = 0; i < HALF; ++i) {
        float send = up ? a[i] : a[i + HALF];
        float recv = __shfl_xor_sync(0xffffffffu, send, M);
        a[i] = (up ? a[i + HALF] : a[i]) + recv;
    }
}

__global__ void __launch_bounds__(NTHREADS, 1)
rnn_kernel(const float* __restrict__ x,
           const float* __restrict__ W_in,
           const float* __restrict__ W_res) {
    // Transposed partials (R14): spart[parity][row][warp], padded to 12 so the
    // publisher reads each row as two conflict-free LDS.128.
    __shared__ __align__(16) float spart[2][ROWS][12];
    __shared__ float swin[ROWS][XDIM];  // this CTA's W_in rows (prologue only)

    const int tid   = threadIdx.x;
    const int w     = tid >> 5;
    const int l     = tid & 31;
    const int rbase = blockIdx.x * ROWS;
    const int c0    = w * 256 + l * 4;          // lane's column base (R1 layout)
    const unsigned ng = (w < 7) ? 16u : 13u;    // producers in this warp's group
    unsigned tgt = 0u;                           // poll target = s * ng

    // ================= prologue: u[s][r] = W_in[r,:] . x[s,:] =================
    // Purely intra-CTA (each CTA computes only its own 16 rows); no grid sync.
    for (int i = tid; i < ROWS * XDIM; i += NTHREADS)
        swin[i / XDIM][i % XDIM] = W_in[(rbase + i / XDIM) * XDIM + i % XDIM];
    __syncthreads();
    for (int s = tid; s < NSTEP; s += NTHREADS) {
        float xv[XDIM];
        const float4* xp = (const float4*)(x + (size_t)s * XDIM);
#pragma unroll
        for (int j = 0; j < 7; ++j) {
            const float4 v = __ldg(xp + j);
            xv[4*j] = v.x; xv[4*j+1] = v.y; xv[4*j+2] = v.z; xv[4*j+3] = v.w;
        }
        float4 uo[4];
#pragma unroll
        for (int r = 0; r < ROWS; ++r) {
            float acc = 0.0f;
#pragma unroll
            for (int i = 0; i < XDIM; ++i) acc = fmaf(swin[r][i], xv[i], acc);
            ((float*)uo)[r] = acc;
        }
        float4* ud = (float4*)(g_u + ((size_t)blockIdx.x * NSTEP + s) * ROWS);
        ud[0] = uo[0]; ud[1] = uo[1]; ud[2] = uo[2]; ud[3] = uo[3];
    }
    __syncthreads();   // u slice visible to this CTA's publisher (same SM L1)

    // ---- W_ext = [W_res | 0] slice in registers (128 regs) ----
    unsigned long long W2[ROWS][4];
#pragma unroll
    for (int r = 0; r < ROWS; ++r) {
        const int gr = rbase + r;
#pragma unroll
        for (int q = 0; q < 4; ++q) {
            const int c = c0 + (q >> 1) * 128 + (q & 1) * 2;
            const float w0 = (c     < RDIM) ? W_res[gr * RDIM + c]     : 0.0f;
            const float w1 = (c + 1 < RDIM) ? W_res[gr * RDIM + c + 1] : 0.0f;
            W2[r][q] = pk2(w0, w1);
        }
    }

    const unsigned* __restrict__ cp = &g_ctr[w * 32];
    unsigned* __restrict__ ap = &g_ctr[(blockIdx.x >> 4) * 32];
    const float* __restrict__ ubase = g_u + (size_t)blockIdx.x * NSTEP * ROWS;

    // publisher (warp 0, lanes 0-15): u for step 0 preloaded
    float ureg = 0.0f;
    if (w == 0 && l < ROWS) ureg = ubase[l];

    for (int s = 0; s < NSTEP; ++s) {
        // ---- per-warp gate (FROZEN protocol) ----
        while (ld_acq(cp) < tgt) { }
        tgt += ng;

        // ---- load this lane's 8 h-columns (uniform across ALL warps:
        //      cols 2000..2047 are permanently 0.0 and their W is 0) ----
        const float* __restrict__ buf = g_h[(s + 1) & 1];
        const ulonglong2 ha = __ldcg((const ulonglong2*)(buf + c0));
        const ulonglong2 hb = __ldcg((const ulonglong2*)(buf + c0 + 128));

        // ---- matvec: 16 rows x 8 cols per lane, packed f32x2 (R1 order) ----
        unsigned long long acc[ROWS];
#pragma unroll
        for (int r = 0; r < ROWS; ++r) acc[r] = mul2(W2[r][0], ha.x);
#pragma unroll
        for (int r = 0; r < ROWS; ++r) acc[r] = fma2(W2[r][1], ha.y, acc[r]);
#pragma unroll
        for (int r = 0; r < ROWS; ++r) acc[r] = fma2(W2[r][2], hb.x, acc[r]);
#pragma unroll
        for (int r = 0; r < ROWS; ++r) acc[r] = fma2(W2[r][3], hb.y, acc[r]);

        float a[ROWS];
#pragma unroll
        for (int r = 0; r < ROWS; ++r) a[r] = lo32(acc[r]) + hi32(acc[r]);

        // ---- R1-validated warp reduce-scatter (16 rows over 32 lanes) ----
        rs_stage<16, 8>(a, l);
        rs_stage<8, 4>(a, l);
        rs_stage<4, 2>(a, l);
        rs_stage<2, 1>(a, l);
        const float pv = a[0] + __shfl_xor_sync(0xffffffffu, a[0], 1);

        // parity double-buffer write (no front barrier; R11-proven)
        if ((l & 1) == 0) spart[s & 1][l >> 1][w] = pv;

        // ---- split barrier (R14): non-publishers arrive and run ahead ----
        const int bid = 1 + (s & 1);
        if (w != 0) {
            asm volatile("bar.arrive %0, %1;" :: "r"(bid), "r"(NTHREADS) : "memory");
            continue;   // straight to next-step poll
        }
        asm volatile("bar.sync %0, %1;" :: "r"(bid), "r"(NTHREADS) : "memory");

        // ---- warp 0: combine + u + tanh + publish + release ----
        {
            float hv = 0.0f;
            if (l < ROWS) {
                const float4 p0 = *(const float4*)&spart[s & 1][l][0];
                const float4 p1 = *(const float4*)&spart[s & 1][l][4];
                const float sum = ((p0.x + p0.y) + (p0.z + p0.w))
                                + ((p1.x + p1.y) + (p1.z + p1.w)) + ureg;
                hv = ftanh(sum);
                __stcg(&g_h[s & 1][rbase + l], hv);
            }
            __syncwarp();
            if (l == 0)
                asm volatile("red.release.gpu.global.add.u32 [%0], %1;"
                             :: "l"(ap), "r"(1u) : "memory");
            // off-path: hlast store + u prefetch for step s+1
            if (l < ROWS) {
                if ((s % TSTEPS) == TSTEPS - 1)
                    g_hlast[(s / TSTEPS) * RDIM + rbase + l] = hv;
                if (s + 1 < NSTEP)
                    ureg = ubase[(size_t)(s + 1) * ROWS + l];
            }
        }
    }
}

__global__ void out_kernel(const float* __restrict__ W_out,
                           float* __restrict__ out) {
    const int b   = blockIdx.x;
    const int tid = threadIdx.x;
    const float* __restrict__ h = g_hlast + b * RDIM;

    float acc[ODIM];
#pragma unroll
    for (int o = 0; o < ODIM; ++o) acc[o] = 0.f;

    for (int k = tid; k < RDIM; k += 256) {
        const float hv = h[k];
#pragma unroll
        for (int o = 0; o < ODIM; ++o)
            acc[o] = fmaf(W_out[o * RDIM + k], hv, acc[o]);
    }
#pragma unroll
    for (int o = 0; o < ODIM; ++o) {
#pragma unroll
        for (int m = 16; m >= 1; m >>= 1)
            acc[o] += __shfl_xor_sync(0xffffffffu, acc[o], m);
    }
    __shared__ float sp[8][ODIM];
    if ((tid & 31) == 0) {
#pragma unroll
        for (int o = 0; o < ODIM; ++o) sp[tid >> 5][o] = acc[o];
    }
    __syncthreads();
    if (tid < ODIM) {
        float s2 = 0.f;
#pragma unroll
        for (int ww = 0; ww < 8; ++ww) s2 += sp[ww][tid];
        out[b * ODIM + tid] = s2;
    }
}

__global__ void reset_kernel() {   // restores state for the NEXT replay
    const int t = blockIdx.x * blockDim.x + threadIdx.x;
    if (t < NGRP * 32) g_ctr[t] = 0u;
    if (t < RDIM)      g_h[1][t] = 0.0f;   // h0 = 0 (buffer read by step 0)
}

extern "C" void kernel_launch(void* const* d_in, const int* in_sizes, int n_in,
                              void* d_out, int out_size) {
    (void)in_sizes; (void)n_in; (void)out_size;
    const float* x     = (const float*)d_in[0];
    const float* W_in  = (const float*)d_in[1];
    const float* W_res = (const float*)d_in[2];
    const float* W_out = (const float*)d_in[3];
    float* out = (float*)d_out;

    // Order (rnn, out, reset): profiler lands on rnn; reset prepares the next
    // replay; first launch relies on zero-initialized device globals.
    rnn_kernel<<<NCTA, NTHREADS>>>(x, W_in, W_res);  // 125 CTAs, 1/SM
    out_kernel<<<BATCH, 256>>>(W_out, out);
    reset_kernel<<<8, 256>>>();
}